// round 13
// baseline (speedup 1.0000x reference)
#include <cuda_runtime.h>
#include <cuda_fp16.h>
#include <cstdint>
#include <math.h>

// SphericalFilter via mma.sync.m16n8k16 fp16 (fp32 accumulate).
// out[p,h] = sum_k Y[p,k] * W[h,k] + b[h];  P=131072, H=1024, K=129 (pad 144)
//
// R13: 64x64 warptile (4mt x 8nt) -> 128 B LDS per HMMA (was 192). 256-thread
// CTA, 1 CTA/SM (acc=128 regs). h-tiles of 256 h (warps 2M x 4N). B ring:
// 24KB blocks (3 kc x 8KB), 4 stages, cp.async.bulk, free-running warps,
// streaming STG epilogue. Y-recurrence constants tabulated.

#define NK 129
#define NKPAD 144
#define NKC 9               // k-chunks of 16 per h-tile
#define KCB 3               // kc per ring block
#define H_TOT 1024
#define TILE_P 128
#define NTHREADS 256
#define NHT 4               // 256-h tiles per CTA
#define NBLK (NHT * NKC / KCB)        // 12 blocks
#define STAGES 4
#define PROD_AHEAD 2
#define KC_BYTES 8192                 // B bytes per kc (256 h)
#define BLK_BYTES (KCB * KC_BYTES)    // 24576

#define AFRAG_HALFS (8 * NKC * 32 * 8)          // 36864 B
#define RING_OFF (AFRAG_HALFS * 2)              // 36864
#define RING_BYTES (STAGES * BLK_BYTES)         // 98304
#define MBAR_OFF (RING_OFF + RING_BYTES)        // 135168
#define SMEM_BYTES (MBAR_OFF + 128)             // 135296 B

// Wfrag2: [ht2 0..3][kc 0..8] 8KB blocks; inside [wN 0..3][nt 0..7][lane][reg]
__device__ uint32_t Wfrag2[NHT * NKC * 2048];
// Y recurrence constants: x = -sqrt((2m+1)/(2m)), y = (+-sqrt2)*sqrt(2m+3)
__device__ float2 Ycst[65];

// ---------------- helpers ----------------
__device__ __forceinline__ uint32_t smem_u32(const void* p) {
    uint32_t a;
    asm("{ .reg .u64 t; cvta.to.shared.u64 t, %1; cvt.u32.u64 %0, t; }" : "=r"(a) : "l"(p));
    return a;
}
__device__ __forceinline__ void mbar_init(uint32_t mbar, uint32_t cnt) {
    asm volatile("mbarrier.init.shared.b64 [%0], %1;" :: "r"(mbar), "r"(cnt) : "memory");
}
__device__ __forceinline__ void mbar_arrive(uint32_t mbar) {
    asm volatile("mbarrier.arrive.shared.b64 _, [%0];" :: "r"(mbar) : "memory");
}
__device__ __forceinline__ void mbar_expect_tx(uint32_t mbar, uint32_t bytes) {
    asm volatile("mbarrier.arrive.expect_tx.shared.b64 _, [%0], %1;"
                 :: "r"(mbar), "r"(bytes) : "memory");
}
__device__ __forceinline__ void mbar_wait(uint32_t mbar, uint32_t parity) {
    asm volatile(
        "{\n\t.reg .pred P;\n"
        "WL_%=:\n\t"
        "mbarrier.try_wait.parity.acquire.cta.shared::cta.b64 P, [%0], %1, 0x989680;\n\t"
        "@P bra.uni WD_%=;\n\t"
        "bra.uni WL_%=;\n"
        "WD_%=:\n\t}"
        :: "r"(mbar), "r"(parity) : "memory");
}
__device__ __forceinline__ void bulk_copy(uint32_t dst, const void* src,
                                          uint32_t bytes, uint32_t mbar) {
    asm volatile(
        "cp.async.bulk.shared::cta.global.mbarrier::complete_tx::bytes [%0], [%1], %2, [%3];"
        :: "r"(dst), "l"(src), "r"(bytes), "r"(mbar) : "memory");
}

// A-fragment half index for element (row, k); one LDS.128 per (mt,kc,lane).
__device__ __forceinline__ int a_off(int row, int k) {
    int mt = row >> 4, half8 = (row >> 3) & 1, g = row & 7;
    int kc = k >> 4, khalf = (k >> 3) & 1, t = (k >> 1) & 3, kbit = k & 1;
    int lane = g * 4 + t;
    int reg = khalf * 2 + half8;
    return (((mt * NKC + kc) * 32 + lane) * 4 + reg) * 2 + kbit;
}

__device__ __forceinline__ void mma16(const uint32_t* a, const uint32_t* b, float* c) {
    asm volatile(
        "mma.sync.aligned.m16n8k16.row.col.f32.f16.f16.f32 "
        "{%0,%1,%2,%3}, {%4,%5,%6,%7}, {%8,%9}, {%0,%1,%2,%3};"
        : "+f"(c[0]), "+f"(c[1]), "+f"(c[2]), "+f"(c[3])
        : "r"(a[0]), "r"(a[1]), "r"(a[2]), "r"(a[3]), "r"(b[0]), "r"(b[1]));
}

__device__ __forceinline__ void stcs4(float* p, float4 v) {
    asm volatile("st.global.cs.v4.f32 [%0], {%1,%2,%3,%4};"
                 :: "l"(p), "f"(v.x), "f"(v.y), "f"(v.z), "f"(v.w) : "memory");
}

// ---------------- W -> B-fragment reorder + Y constant table ----------------
// h = ht2*256 + wN*64 + hl;  hl = t*16 + nt*2 + j  (t = C-frag lane&3, nt 0..7)
__global__ void wfrag_kernel(const float* __restrict__ W) {
    int idx = blockIdx.x * blockDim.x + threadIdx.x;
    if (blockIdx.x == 0 && threadIdx.x >= 1 && threadIdx.x <= 64) {
        int m = threadIdx.x;
        float2 c;
        c.x = -sqrtf((2.0f * m + 1.0f) / (2.0f * m));
        c.y = ((m & 1) ? -1.41421356237309515f : 1.41421356237309515f)
              * sqrtf(2.0f * m + 3.0f);
        Ycst[m] = c;
    }
    if (idx >= H_TOT * NKPAD) return;
    int h = idx / NKPAD;
    int k = idx - h * NKPAD;
    float v = (k < NK) ? W[h * NK + k] : 0.0f;
    int ht2 = h >> 8;
    int wN = (h >> 6) & 3;
    int hl = h & 63;
    int t = hl >> 4;
    int rem = hl & 15;
    int nt = rem >> 1;
    int j = rem & 1;
    int n = t * 2 + j;                 // column within m16n8 tile
    int lane = n * 4 + ((k >> 1) & 3);
    int reg = (k >> 3) & 1;
    int kbit = k & 1;
    int kc = k >> 4;
    uint32_t* dst = &Wfrag2[(ht2 * NKC + kc) * 2048 + ((wN * 8 + nt) * 32 + lane) * 2 + reg];
    __half* hp = (__half*)dst;
    hp[kbit] = __float2half_rn(v);
}

// ---------------- main fused kernel ----------------
__global__ __launch_bounds__(NTHREADS, 1)
void sph_mma_kernel(const float* __restrict__ x,
                    const float* __restrict__ bvec,
                    float* __restrict__ out) {
    extern __shared__ __half smemh[];
    __half* Afrag = smemh;
    const uint32_t sbase = smem_u32(smemh);
    const uint32_t ring = sbase + RING_OFF;
    const uint32_t full0 = sbase + MBAR_OFF;
    const uint32_t empty0 = sbase + MBAR_OFF + 64;

    const int tid = threadIdx.x;
    const int lane = tid & 31;
    const int wid = tid >> 5;
    const int wN = wid >> 1;         // N quarter of a 256-h tile (64 h)
    const int wmt = (wid & 1) * 4;   // M base in mtiles (4 mtiles = 64 rows)
    const int pbase = blockIdx.x * TILE_P;
    const bool producer = (tid == 0);
    const char* gW = (const char*)Wfrag2;

    if (tid == 0) {
        #pragma unroll
        for (int s = 0; s < STAGES; ++s) {
            mbar_init(full0 + s * 8, 1);    // expect_tx based
            mbar_init(empty0 + s * 8, 8);   // 8 consumer warps
        }
    }
    __syncthreads();

    if (producer) {
        #pragma unroll
        for (int b = 0; b < PROD_AHEAD; ++b) {
            mbar_expect_tx(full0 + b * 8, BLK_BYTES);
            bulk_copy(ring + b * BLK_BYTES, gW + (size_t)b * BLK_BYTES,
                      BLK_BYTES, full0 + b * 8);
        }
    }

    // ---- generate Y for 128 pixels into A-fragment layout (threads 0..127) ----
    if (tid < TILE_P) {
        float2 tp = ((const float2*)x)[pbase + tid];
        const float theta = tp.x, phi = tp.y;
        const float ct = cosf(phi);
        const float st = sqrtf(fmaxf(1.0f - ct * ct, 0.0f));
        float pmm = 0.28209479177387814f;                 // sqrt(1/4pi)
        Afrag[a_off(tid, 64)] = __float2half_rn(1.7320508075688772f * ct * pmm);
        const float cth = cosf(theta), sth = sinf(theta);
        float cm = 1.0f, sm = 0.0f;
        const float2* __restrict__ yc = Ycst;
        #pragma unroll 4
        for (int m = 1; m <= 64; ++m) {
            float2 c = __ldg(&yc[m]);
            pmm *= c.x * st;
            float c2 = cm * cth - sm * sth;
            float s2 = sm * cth + cm * sth;
            cm = c2; sm = s2;
            float v = c.y * ct * pmm;
            Afrag[a_off(tid, 64 + m)] = __float2half_rn(v * cm);
            Afrag[a_off(tid, 64 - m)] = __float2half_rn(v * sm);
        }
        #pragma unroll
        for (int k = NK; k < NKPAD; ++k) Afrag[a_off(tid, k)] = __half(0.0f);
    }
    __syncthreads();

    const uint32_t abase = sbase;   // Afrag at smem offset 0

    #pragma unroll 1
    for (int ht = 0; ht < NHT; ++ht) {
        float acc[4][8][4];
        #pragma unroll
        for (int mt = 0; mt < 4; ++mt)
            #pragma unroll
            for (int nt = 0; nt < 8; ++nt)
                #pragma unroll
                for (int i = 0; i < 4; ++i) acc[mt][nt][i] = 0.0f;

        #pragma unroll
        for (int kcb = 0; kcb < NKC / KCB; ++kcb) {
            const int b = ht * (NKC / KCB) + kcb;   // ring block index
            const int stage = b & (STAGES - 1);

            if (producer) {
                const int bp = b + PROD_AHEAD;
                if (bp < NBLK) {
                    const int sp = bp & (STAGES - 1);
                    const int u = bp >> 2;
                    if (u >= 1) mbar_wait(empty0 + sp * 8, (u - 1) & 1);
                    mbar_expect_tx(full0 + sp * 8, BLK_BYTES);
                    bulk_copy(ring + sp * BLK_BYTES, gW + (size_t)bp * BLK_BYTES,
                              BLK_BYTES, full0 + sp * 8);
                }
            }

            mbar_wait(full0 + stage * 8, (b >> 2) & 1);

            #pragma unroll
            for (int kci = 0; kci < KCB; ++kci) {
                const int kc = kcb * KCB + kci;

                const uint32_t bs = ring + stage * BLK_BYTES + kci * KC_BYTES
                                  + wN * 2048 + lane * 8;
                uint32_t bfr[8][2];
                #pragma unroll
                for (int nt = 0; nt < 8; ++nt)
                    asm volatile("ld.shared.v2.u32 {%0,%1}, [%2];"
                                 : "=r"(bfr[nt][0]), "=r"(bfr[nt][1])
                                 : "r"(bs + nt * 256));

                uint32_t afr[4][4];
                #pragma unroll
                for (int mt = 0; mt < 4; ++mt) {
                    uint32_t addr = abase + ((((wmt + mt) * NKC + kc) * 32 + lane) * 4) * 4;
                    asm volatile("ld.shared.v4.u32 {%0,%1,%2,%3}, [%4];"
                                 : "=r"(afr[mt][0]), "=r"(afr[mt][1]),
                                   "=r"(afr[mt][2]), "=r"(afr[mt][3])
                                 : "r"(addr));
                }

                #pragma unroll
                for (int mt = 0; mt < 4; ++mt)
                    #pragma unroll
                    for (int nt = 0; nt < 8; ++nt)
                        mma16(afr[mt], bfr[nt], acc[mt][nt]);
            }

            if (lane == 0) mbar_arrive(empty0 + stage * 8);
        }

        // ---- epilogue: 16 consecutive h per lane -> 4x streaming STG.128/row ----
        const int g8 = lane >> 2;
        const int hb = ht * 256 + wN * 64 + (lane & 3) * 16;
        float4 bb[4];
        #pragma unroll
        for (int g = 0; g < 4; ++g) bb[g] = *(const float4*)&bvec[hb + 4 * g];
        #pragma unroll
        for (int mt = 0; mt < 4; ++mt) {
            const int p0 = pbase + (wmt + mt) * 16 + g8;
            float* o0 = &out[(size_t)p0 * H_TOT + hb];
            float* o1 = &out[(size_t)(p0 + 8) * H_TOT + hb];
            #pragma unroll
            for (int g = 0; g < 4; ++g) {
                float4 v0, v1;
                v0.x = acc[mt][(g * 4 + 0) >> 1][(g * 4 + 0) & 1] + bb[g].x;
                v0.y = acc[mt][(g * 4 + 1) >> 1][(g * 4 + 1) & 1] + bb[g].y;
                v0.z = acc[mt][(g * 4 + 2) >> 1][(g * 4 + 2) & 1] + bb[g].z;
                v0.w = acc[mt][(g * 4 + 3) >> 1][(g * 4 + 3) & 1] + bb[g].w;
                v1.x = acc[mt][(g * 4 + 0) >> 1][2 + ((g * 4 + 0) & 1)] + bb[g].x;
                v1.y = acc[mt][(g * 4 + 1) >> 1][2 + ((g * 4 + 1) & 1)] + bb[g].y;
                v1.z = acc[mt][(g * 4 + 2) >> 1][2 + ((g * 4 + 2) & 1)] + bb[g].z;
                v1.w = acc[mt][(g * 4 + 3) >> 1][2 + ((g * 4 + 3) & 1)] + bb[g].w;
                stcs4(o0 + 4 * g, v0);
                stcs4(o1 + 4 * g, v1);
            }
        }
    }
}

extern "C" void kernel_launch(void* const* d_in, const int* in_sizes, int n_in,
                              void* d_out, int out_size) {
    const float* x = (const float*)d_in[0];   // (P, 2)
    const float* W = (const float*)d_in[1];   // (1024, 129)
    const float* b = (const float*)d_in[2];   // (1024,)
    float* out = (float*)d_out;               // (P, 1024)

    const int P = in_sizes[0] / 2;            // 131072

    wfrag_kernel<<<(H_TOT * NKPAD + 255) / 256, 256>>>(W);

    cudaFuncSetAttribute(sph_mma_kernel,
                         cudaFuncAttributeMaxDynamicSharedMemorySize, SMEM_BYTES);
    sph_mma_kernel<<<P / TILE_P, NTHREADS, SMEM_BYTES>>>(x, b, out);
}

// round 14
// speedup vs baseline: 1.3689x; 1.3689x over previous
#include <cuda_runtime.h>
#include <cuda_fp16.h>
#include <cstdint>
#include <math.h>

// SphericalFilter via mma.sync.m16n8k16 fp16 (fp32 accumulate).
// out[p,h] = sum_k Y[p,k] * W[h,k] + b[h];  P=131072, H=1024, K=129 (pad 144)
//
// R14: three kernels.
//  1) wfrag: W -> B-fragment layout (+ Y constant table).
//  2) ygen:  Y -> A-fragment layout per 128-pixel tile, staged in smem,
//     bulk-copied to gmem Ybuf (37.7MB, L2-resident).
//  3) sph_mma: pure GEMM. Grid 2048 (128p x 512h) -> ~2% tail. A via one
//     cp.async.bulk; B via 12KB-block ring (3 kc), 4 stages; free-running
//     warps; streaming STG epilogue. 256-thr CTAs, 64x32 warptile, 2 CTA/SM.

#define NK 129
#define NKPAD 144
#define NKC 9               // k-chunks of 16 per 128-h tile
#define KCB 3               // kc per ring block
#define H_TOT 1024
#define TILE_P 128
#define NTHREADS 256
#define NHT 4               // 128-h tiles per CTA (512 h total)
#define NBLK (NHT * NKC / KCB)        // 12 ring blocks per CTA
#define STAGES 4
#define PROD_AHEAD 2
#define BLK_BYTES (KCB * 4096)        // 12288

#define AFRAG_HALFS (8 * NKC * 32 * 8)          // 18432 halfs = 36864 B
#define ATILE_BYTES (AFRAG_HALFS * 2)           // 36864
#define RING_OFF ATILE_BYTES                    // 36864
#define RING_BYTES (STAGES * BLK_BYTES)         // 49152
#define MBAR_OFF (RING_OFF + RING_BYTES)        // 86016: full[4], empty[4], fullA
#define SMEM_BYTES (MBAR_OFF + 160)             // 86176 B

// Wfrag2: [htg 0..7][kc 0..8][wQ] 4KB units; inside: [nt][lane][reg] f16x2
__device__ __half Wfrag2[8 * NKC * 4 * 512];
// Y in A-fragment layout, one 36864B tile per 128 pixels
__device__ __half Ybuf[1024 * AFRAG_HALFS];     // 37.75 MB
// Y recurrence constants: x = -sqrt((2m+1)/(2m)), y = (+-sqrt2)*sqrt(2m+3)
__device__ float2 Ycst[65];

// ---------------- helpers ----------------
__device__ __forceinline__ uint32_t smem_u32(const void* p) {
    uint32_t a;
    asm("{ .reg .u64 t; cvta.to.shared.u64 t, %1; cvt.u32.u64 %0, t; }" : "=r"(a) : "l"(p));
    return a;
}
__device__ __forceinline__ void mbar_init(uint32_t mbar, uint32_t cnt) {
    asm volatile("mbarrier.init.shared.b64 [%0], %1;" :: "r"(mbar), "r"(cnt) : "memory");
}
__device__ __forceinline__ void mbar_arrive(uint32_t mbar) {
    asm volatile("mbarrier.arrive.shared.b64 _, [%0];" :: "r"(mbar) : "memory");
}
__device__ __forceinline__ void mbar_expect_tx(uint32_t mbar, uint32_t bytes) {
    asm volatile("mbarrier.arrive.expect_tx.shared.b64 _, [%0], %1;"
                 :: "r"(mbar), "r"(bytes) : "memory");
}
__device__ __forceinline__ void mbar_wait(uint32_t mbar, uint32_t parity) {
    asm volatile(
        "{\n\t.reg .pred P;\n"
        "WL_%=:\n\t"
        "mbarrier.try_wait.parity.acquire.cta.shared::cta.b64 P, [%0], %1, 0x989680;\n\t"
        "@P bra.uni WD_%=;\n\t"
        "bra.uni WL_%=;\n"
        "WD_%=:\n\t}"
        :: "r"(mbar), "r"(parity) : "memory");
}
__device__ __forceinline__ void bulk_copy(uint32_t dst, const void* src,
                                          uint32_t bytes, uint32_t mbar) {
    asm volatile(
        "cp.async.bulk.shared::cta.global.mbarrier::complete_tx::bytes [%0], [%1], %2, [%3];"
        :: "r"(dst), "l"(src), "r"(bytes), "r"(mbar) : "memory");
}
__device__ __forceinline__ void bulk_s2g(void* dst, uint32_t src, uint32_t bytes) {
    asm volatile("cp.async.bulk.global.shared::cta.bulk_group [%0], [%1], %2;"
                 :: "l"(dst), "r"(src), "r"(bytes) : "memory");
}
__device__ __forceinline__ void bulk_commit() {
    asm volatile("cp.async.bulk.commit_group;" ::: "memory");
}
__device__ __forceinline__ void bulk_waitall() {
    asm volatile("cp.async.bulk.wait_group 0;" ::: "memory");
}
__device__ __forceinline__ void fence_async() {
    asm volatile("fence.proxy.async.shared::cta;" ::: "memory");
}

// A-fragment half index for element (row, k); one LDS.128 per (mt,kc,lane).
__device__ __forceinline__ int a_off(int row, int k) {
    int mt = row >> 4, half8 = (row >> 3) & 1, g = row & 7;
    int kc = k >> 4, khalf = (k >> 3) & 1, t = (k >> 1) & 3, kbit = k & 1;
    int lane = g * 4 + t;
    int reg = khalf * 2 + half8;
    return (((mt * NKC + kc) * 32 + lane) * 4 + reg) * 2 + kbit;
}

__device__ __forceinline__ void mma16(const uint32_t* a, const uint32_t* b, float* c) {
    asm volatile(
        "mma.sync.aligned.m16n8k16.row.col.f32.f16.f16.f32 "
        "{%0,%1,%2,%3}, {%4,%5,%6,%7}, {%8,%9}, {%0,%1,%2,%3};"
        : "+f"(c[0]), "+f"(c[1]), "+f"(c[2]), "+f"(c[3])
        : "r"(a[0]), "r"(a[1]), "r"(a[2]), "r"(a[3]), "r"(b[0]), "r"(b[1]));
}

__device__ __forceinline__ void stcs4(float* p, float4 v) {
    asm volatile("st.global.cs.v4.f32 [%0], {%1,%2,%3,%4};"
                 :: "l"(p), "f"(v.x), "f"(v.y), "f"(v.z), "f"(v.w) : "memory");
}

// ---------------- W -> B-fragment reorder + Y constant table ----------------
// h = htg*128 + wQ*32 + hl;  hl = t*8 + nt*2 + j  (t = C-frag lane&3)
__global__ void wfrag_kernel(const float* __restrict__ W) {
    int idx = blockIdx.x * blockDim.x + threadIdx.x;
    if (blockIdx.x == 0 && threadIdx.x >= 1 && threadIdx.x <= 64) {
        int m = threadIdx.x;
        float2 c;
        c.x = -sqrtf((2.0f * m + 1.0f) / (2.0f * m));
        c.y = ((m & 1) ? -1.41421356237309515f : 1.41421356237309515f)
              * sqrtf(2.0f * m + 3.0f);
        Ycst[m] = c;
    }
    if (idx >= H_TOT * NKPAD) return;
    int h = idx / NKPAD;
    int k = idx - h * NKPAD;
    float v = (k < NK) ? W[h * NK + k] : 0.0f;
    int htg = h >> 7;
    int wQ = (h >> 5) & 3;
    int hl = h & 31;
    int t = hl >> 3;
    int rem = hl & 7;
    int nt = rem >> 1;
    int j = rem & 1;
    int n = t * 2 + j;
    int lane = n * 4 + ((k >> 1) & 3);
    int reg = (k >> 3) & 1;
    int kbit = k & 1;
    int kc = k >> 4;
    int block = (htg * NKC + kc) * 4 + wQ;
    Wfrag2[block * 512 + ((nt * 32 + lane) * 2 + reg) * 2 + kbit] = __float2half_rn(v);
}

// ---------------- Y generation: 128 pixels/block -> Ybuf tile ----------------
__global__ __launch_bounds__(128, 6)
void ygen_kernel(const float* __restrict__ x) {
    __shared__ __half Af[AFRAG_HALFS];
    const int tid = threadIdx.x;
    const int tile = blockIdx.x;

    float2 tp = ((const float2*)x)[tile * TILE_P + tid];
    const float theta = tp.x, phi = tp.y;
    const float ct = cosf(phi);
    const float st = sqrtf(fmaxf(1.0f - ct * ct, 0.0f));
    float pmm = 0.28209479177387814f;                 // sqrt(1/4pi)
    Af[a_off(tid, 64)] = __float2half_rn(1.7320508075688772f * ct * pmm);
    const float cth = cosf(theta), sth = sinf(theta);
    float cm = 1.0f, sm = 0.0f;
    const float2* __restrict__ yc = Ycst;
    #pragma unroll 4
    for (int m = 1; m <= 64; ++m) {
        float2 c = __ldg(&yc[m]);
        pmm *= c.x * st;
        float c2 = cm * cth - sm * sth;
        float s2 = sm * cth + cm * sth;
        cm = c2; sm = s2;
        float v = c.y * ct * pmm;
        Af[a_off(tid, 64 + m)] = __float2half_rn(v * cm);
        Af[a_off(tid, 64 - m)] = __float2half_rn(v * sm);
    }
    #pragma unroll
    for (int k = NK; k < NKPAD; ++k) Af[a_off(tid, k)] = __half(0.0f);

    __syncthreads();
    fence_async();
    if (tid == 0) {
        bulk_s2g(&Ybuf[(size_t)tile * AFRAG_HALFS], smem_u32(Af), ATILE_BYTES);
        bulk_commit();
        bulk_waitall();
    }
}

// ---------------- main GEMM kernel ----------------
__global__ __launch_bounds__(NTHREADS, 2)
void sph_mma_kernel(const float* __restrict__ bvec,
                    float* __restrict__ out) {
    extern __shared__ __half smemh[];
    const uint32_t sbase = smem_u32(smemh);
    const uint32_t ring = sbase + RING_OFF;
    const uint32_t full0 = sbase + MBAR_OFF;
    const uint32_t empty0 = sbase + MBAR_OFF + 64;
    const uint32_t fullA = sbase + MBAR_OFF + 128;

    const int tid = threadIdx.x;
    const int lane = tid & 31;
    const int wid = tid >> 5;
    const int wQ = wid & 3;          // N quarter (32 h within a 128-h tile)
    const int wmt = (wid >> 2) * 4;  // M base in mtiles
    const int bid = blockIdx.x;
    const int ptile = bid >> 1;
    const int pbase = ptile * TILE_P;
    const int hhalf = bid & 1;       // which 512-h half
    const bool producer = (tid == 0);
    const char* gW = (const char*)Wfrag2 + (size_t)hhalf * NBLK * BLK_BYTES;

    if (tid == 0) {
        #pragma unroll
        for (int s = 0; s < STAGES; ++s) {
            mbar_init(full0 + s * 8, 1);    // expect_tx based
            mbar_init(empty0 + s * 8, 8);   // 8 consumer warps
        }
        mbar_init(fullA, 1);
    }
    __syncthreads();

    if (producer) {
        // A tile (one copy) + first W ring blocks
        mbar_expect_tx(fullA, ATILE_BYTES);
        bulk_copy(sbase, &Ybuf[(size_t)ptile * AFRAG_HALFS], ATILE_BYTES, fullA);
        #pragma unroll
        for (int b = 0; b < PROD_AHEAD; ++b) {
            mbar_expect_tx(full0 + b * 8, BLK_BYTES);
            bulk_copy(ring + b * BLK_BYTES, gW + (size_t)b * BLK_BYTES,
                      BLK_BYTES, full0 + b * 8);
        }
    }

    mbar_wait(fullA, 0);   // all threads: A resident

    const uint32_t abase = sbase;   // Afrag at smem offset 0

    #pragma unroll 1
    for (int ht = 0; ht < NHT; ++ht) {
        float acc[4][4][4];
        #pragma unroll
        for (int mt = 0; mt < 4; ++mt)
            #pragma unroll
            for (int nt = 0; nt < 4; ++nt)
                #pragma unroll
                for (int i = 0; i < 4; ++i) acc[mt][nt][i] = 0.0f;

        #pragma unroll
        for (int kcb = 0; kcb < NKC / KCB; ++kcb) {
            const int b = ht * (NKC / KCB) + kcb;   // ring block index
            const int stage = b & (STAGES - 1);

            if (producer) {
                const int bp = b + PROD_AHEAD;
                if (bp < NBLK) {
                    const int sp = bp & (STAGES - 1);
                    const int u = bp >> 2;
                    if (u >= 1) mbar_wait(empty0 + sp * 8, (u - 1) & 1);
                    mbar_expect_tx(full0 + sp * 8, BLK_BYTES);
                    bulk_copy(ring + sp * BLK_BYTES, gW + (size_t)bp * BLK_BYTES,
                              BLK_BYTES, full0 + sp * 8);
                }
            }

            mbar_wait(full0 + stage * 8, (b >> 2) & 1);

            #pragma unroll
            for (int kci = 0; kci < KCB; ++kci) {
                const int kc = kcb * KCB + kci;

                const uint32_t bs = ring + stage * BLK_BYTES + kci * 4096
                                  + wQ * 1024 + lane * 8;
                uint32_t bfr[4][2];
                #pragma unroll
                for (int nt = 0; nt < 4; ++nt)
                    asm volatile("ld.shared.v2.u32 {%0,%1}, [%2];"
                                 : "=r"(bfr[nt][0]), "=r"(bfr[nt][1])
                                 : "r"(bs + nt * 256));

                uint32_t afr[4][4];
                #pragma unroll
                for (int mt = 0; mt < 4; ++mt) {
                    uint32_t addr = abase + ((((wmt + mt) * NKC + kc) * 32 + lane) * 4) * 4;
                    asm volatile("ld.shared.v4.u32 {%0,%1,%2,%3}, [%4];"
                                 : "=r"(afr[mt][0]), "=r"(afr[mt][1]),
                                   "=r"(afr[mt][2]), "=r"(afr[mt][3])
                                 : "r"(addr));
                }

                #pragma unroll
                for (int mt = 0; mt < 4; ++mt)
                    #pragma unroll
                    for (int nt = 0; nt < 4; ++nt)
                        mma16(afr[mt], bfr[nt], acc[mt][nt]);
            }

            if (lane == 0) mbar_arrive(empty0 + stage * 8);
        }

        // ---- epilogue: 8 consecutive h per lane -> 2x streaming STG.128/row ----
        const int g8 = lane >> 2;
        const int hb = hhalf * 512 + ht * 128 + wQ * 32 + (lane & 3) * 8;
        float4 bb0 = *(const float4*)&bvec[hb];
        float4 bb1 = *(const float4*)&bvec[hb + 4];
        #pragma unroll
        for (int mt = 0; mt < 4; ++mt) {
            const int p0 = pbase + (wmt + mt) * 16 + g8;
            float* o0 = &out[(size_t)p0 * H_TOT + hb];
            float* o1 = &out[(size_t)(p0 + 8) * H_TOT + hb];
            float4 v0, v1;
            // row g8
            v0.x = acc[mt][0][0] + bb0.x;  v0.y = acc[mt][0][1] + bb0.y;
            v0.z = acc[mt][1][0] + bb0.z;  v0.w = acc[mt][1][1] + bb0.w;
            v1.x = acc[mt][2][0] + bb1.x;  v1.y = acc[mt][2][1] + bb1.y;
            v1.z = acc[mt][3][0] + bb1.z;  v1.w = acc[mt][3][1] + bb1.w;
            stcs4(o0 + 0, v0);
            stcs4(o0 + 4, v1);
            // row g8+8
            v0.x = acc[mt][0][2] + bb0.x;  v0.y = acc[mt][0][3] + bb0.y;
            v0.z = acc[mt][1][2] + bb0.z;  v0.w = acc[mt][1][3] + bb0.w;
            v1.x = acc[mt][2][2] + bb1.x;  v1.y = acc[mt][2][3] + bb1.y;
            v1.z = acc[mt][3][2] + bb1.z;  v1.w = acc[mt][3][3] + bb1.w;
            stcs4(o1 + 0, v0);
            stcs4(o1 + 4, v1);
        }
    }
}

extern "C" void kernel_launch(void* const* d_in, const int* in_sizes, int n_in,
                              void* d_out, int out_size) {
    const float* x = (const float*)d_in[0];   // (P, 2)
    const float* W = (const float*)d_in[1];   // (1024, 129)
    const float* b = (const float*)d_in[2];   // (1024,)
    float* out = (float*)d_out;               // (P, 1024)

    const int P = in_sizes[0] / 2;            // 131072
    const int ntiles = P / TILE_P;            // 1024

    wfrag_kernel<<<(H_TOT * NKPAD + 255) / 256, 256>>>(W);
    ygen_kernel<<<ntiles, 128>>>(x);

    cudaFuncSetAttribute(sph_mma_kernel,
                         cudaFuncAttributeMaxDynamicSharedMemorySize, SMEM_BYTES);
    sph_mma_kernel<<<ntiles * 2, NTHREADS, SMEM_BYTES>>>(b, out);
}

// round 15
// speedup vs baseline: 1.4466x; 1.0568x over previous
#include <cuda_runtime.h>
#include <cuda_fp16.h>
#include <cstdint>
#include <math.h>

// SphericalFilter via mma.sync.m16n8k16 fp16 (fp32 accumulate).
// out[p,h] = sum_k Y[p,k] * W[h,k] + b[h];  P=131072, H=1024, K=129 (pad 144)
//
// R15 = R12 shape (1024 CTAs, 128p x 1024h, 2 CTA/SM) with:
//  (a) KCB=9: one 36KB ring block per 128-h tile -> 8 mbar waits/warp (was 24)
//  (b) Y precomputed by ygen kernel into Ybuf (A-fragment layout); the GEMM
//      pulls A with a single cp.async.bulk -- no Y math in the GEMM.
// Ring: 2 stages x 36KB. Free-running warps, streaming STG epilogue.

#define NK 129
#define NKPAD 144
#define NKC 9               // k-chunks of 16 per 128-h tile
#define H_TOT 1024
#define TILE_P 128
#define NTHREADS 256
#define NTILES_H 8
#define NBLK NTILES_H                 // 8 ring blocks (one per ht)
#define STAGES 2
#define BLK_BYTES (NKC * 4096)        // 36864

#define AFRAG_HALFS (8 * NKC * 32 * 8)          // 18432 halfs = 36864 B
#define ATILE_BYTES (AFRAG_HALFS * 2)           // 36864
#define RING_OFF ATILE_BYTES                    // 36864
#define RING_BYTES (STAGES * BLK_BYTES)         // 73728
#define MBAR_OFF (RING_OFF + RING_BYTES)        // 110592: full[2], empty[2], fullA
#define SMEM_BYTES (MBAR_OFF + 160)             // 110752 B

// Wfrag2: [htg 0..7][kc 0..8][wQ] 1KB units; inside: [nt][lane][reg] f16x2
__device__ __half Wfrag2[8 * NKC * 4 * 512];
// Y in A-fragment layout, one 36864B tile per 128 pixels
__device__ __half Ybuf[1024 * AFRAG_HALFS];     // 37.75 MB
// Y recurrence constants: x = -sqrt((2m+1)/(2m)), y = (+-sqrt2)*sqrt(2m+3)
__device__ float2 Ycst[65];

// ---------------- helpers ----------------
__device__ __forceinline__ uint32_t smem_u32(const void* p) {
    uint32_t a;
    asm("{ .reg .u64 t; cvta.to.shared.u64 t, %1; cvt.u32.u64 %0, t; }" : "=r"(a) : "l"(p));
    return a;
}
__device__ __forceinline__ void mbar_init(uint32_t mbar, uint32_t cnt) {
    asm volatile("mbarrier.init.shared.b64 [%0], %1;" :: "r"(mbar), "r"(cnt) : "memory");
}
__device__ __forceinline__ void mbar_arrive(uint32_t mbar) {
    asm volatile("mbarrier.arrive.shared.b64 _, [%0];" :: "r"(mbar) : "memory");
}
__device__ __forceinline__ void mbar_expect_tx(uint32_t mbar, uint32_t bytes) {
    asm volatile("mbarrier.arrive.expect_tx.shared.b64 _, [%0], %1;"
                 :: "r"(mbar), "r"(bytes) : "memory");
}
__device__ __forceinline__ void mbar_wait(uint32_t mbar, uint32_t parity) {
    asm volatile(
        "{\n\t.reg .pred P;\n"
        "WL_%=:\n\t"
        "mbarrier.try_wait.parity.acquire.cta.shared::cta.b64 P, [%0], %1, 0x989680;\n\t"
        "@P bra.uni WD_%=;\n\t"
        "bra.uni WL_%=;\n"
        "WD_%=:\n\t}"
        :: "r"(mbar), "r"(parity) : "memory");
}
__device__ __forceinline__ void bulk_copy(uint32_t dst, const void* src,
                                          uint32_t bytes, uint32_t mbar) {
    asm volatile(
        "cp.async.bulk.shared::cta.global.mbarrier::complete_tx::bytes [%0], [%1], %2, [%3];"
        :: "r"(dst), "l"(src), "r"(bytes), "r"(mbar) : "memory");
}
__device__ __forceinline__ void bulk_s2g(void* dst, uint32_t src, uint32_t bytes) {
    asm volatile("cp.async.bulk.global.shared::cta.bulk_group [%0], [%1], %2;"
                 :: "l"(dst), "r"(src), "r"(bytes) : "memory");
}
__device__ __forceinline__ void bulk_commit() {
    asm volatile("cp.async.bulk.commit_group;" ::: "memory");
}
__device__ __forceinline__ void bulk_waitall() {
    asm volatile("cp.async.bulk.wait_group 0;" ::: "memory");
}
__device__ __forceinline__ void fence_async() {
    asm volatile("fence.proxy.async.shared::cta;" ::: "memory");
}

// A-fragment half index for element (row, k); one LDS.128 per (mt,kc,lane).
__device__ __forceinline__ int a_off(int row, int k) {
    int mt = row >> 4, half8 = (row >> 3) & 1, g = row & 7;
    int kc = k >> 4, khalf = (k >> 3) & 1, t = (k >> 1) & 3, kbit = k & 1;
    int lane = g * 4 + t;
    int reg = khalf * 2 + half8;
    return (((mt * NKC + kc) * 32 + lane) * 4 + reg) * 2 + kbit;
}

__device__ __forceinline__ void mma16(const uint32_t* a, const uint32_t* b, float* c) {
    asm volatile(
        "mma.sync.aligned.m16n8k16.row.col.f32.f16.f16.f32 "
        "{%0,%1,%2,%3}, {%4,%5,%6,%7}, {%8,%9}, {%0,%1,%2,%3};"
        : "+f"(c[0]), "+f"(c[1]), "+f"(c[2]), "+f"(c[3])
        : "r"(a[0]), "r"(a[1]), "r"(a[2]), "r"(a[3]), "r"(b[0]), "r"(b[1]));
}

__device__ __forceinline__ void stcs4(float* p, float4 v) {
    asm volatile("st.global.cs.v4.f32 [%0], {%1,%2,%3,%4};"
                 :: "l"(p), "f"(v.x), "f"(v.y), "f"(v.z), "f"(v.w) : "memory");
}

// ---------------- W -> B-fragment reorder + Y constant table ----------------
// h = htg*128 + wQ*32 + hl;  hl = t*8 + nt*2 + j  (t = C-frag lane&3)
__global__ void wfrag_kernel(const float* __restrict__ W) {
    int idx = blockIdx.x * blockDim.x + threadIdx.x;
    if (blockIdx.x == 0 && threadIdx.x >= 1 && threadIdx.x <= 64) {
        int m = threadIdx.x;
        float2 c;
        c.x = -sqrtf((2.0f * m + 1.0f) / (2.0f * m));
        c.y = ((m & 1) ? -1.41421356237309515f : 1.41421356237309515f)
              * sqrtf(2.0f * m + 3.0f);
        Ycst[m] = c;
    }
    if (idx >= H_TOT * NKPAD) return;
    int h = idx / NKPAD;
    int k = idx - h * NKPAD;
    float v = (k < NK) ? W[h * NK + k] : 0.0f;
    int htg = h >> 7;
    int wQ = (h >> 5) & 3;
    int hl = h & 31;
    int t = hl >> 3;
    int rem = hl & 7;
    int nt = rem >> 1;
    int j = rem & 1;
    int n = t * 2 + j;
    int lane = n * 4 + ((k >> 1) & 3);
    int reg = (k >> 3) & 1;
    int kbit = k & 1;
    int kc = k >> 4;
    int block = (htg * NKC + kc) * 4 + wQ;
    Wfrag2[block * 512 + ((nt * 32 + lane) * 2 + reg) * 2 + kbit] = __float2half_rn(v);
}

// ---------------- Y generation: 128 pixels/block -> Ybuf tile ----------------
__global__ __launch_bounds__(128, 6)
void ygen_kernel(const float* __restrict__ x) {
    __shared__ __half Af[AFRAG_HALFS];
    const int tid = threadIdx.x;
    const int tile = blockIdx.x;

    float2 tp = ((const float2*)x)[tile * TILE_P + tid];
    const float theta = tp.x, phi = tp.y;
    const float ct = cosf(phi);
    const float st = sqrtf(fmaxf(1.0f - ct * ct, 0.0f));
    float pmm = 0.28209479177387814f;                 // sqrt(1/4pi)
    Af[a_off(tid, 64)] = __float2half_rn(1.7320508075688772f * ct * pmm);
    const float cth = cosf(theta), sth = sinf(theta);
    float cm = 1.0f, sm = 0.0f;
    const float2* __restrict__ yc = Ycst;
    #pragma unroll 4
    for (int m = 1; m <= 64; ++m) {
        float2 c = __ldg(&yc[m]);
        pmm *= c.x * st;
        float c2 = cm * cth - sm * sth;
        float s2 = sm * cth + cm * sth;
        cm = c2; sm = s2;
        float v = c.y * ct * pmm;
        Af[a_off(tid, 64 + m)] = __float2half_rn(v * cm);
        Af[a_off(tid, 64 - m)] = __float2half_rn(v * sm);
    }
    #pragma unroll
    for (int k = NK; k < NKPAD; ++k) Af[a_off(tid, k)] = __half(0.0f);

    __syncthreads();
    fence_async();
    if (tid == 0) {
        bulk_s2g(&Ybuf[(size_t)tile * AFRAG_HALFS], smem_u32(Af), ATILE_BYTES);
        bulk_commit();
        bulk_waitall();
    }
}

// ---------------- main GEMM kernel ----------------
__global__ __launch_bounds__(NTHREADS, 2)
void sph_mma_kernel(const float* __restrict__ bvec,
                    float* __restrict__ out) {
    extern __shared__ __half smemh[];
    const uint32_t sbase = smem_u32(smemh);
    const uint32_t ring = sbase + RING_OFF;
    const uint32_t full0 = sbase + MBAR_OFF;
    const uint32_t empty0 = sbase + MBAR_OFF + 64;
    const uint32_t fullA = sbase + MBAR_OFF + 128;

    const int tid = threadIdx.x;
    const int lane = tid & 31;
    const int wid = tid >> 5;
    const int wQ = wid & 3;          // N quarter (32 h within a 128-h tile)
    const int wmt = (wid >> 2) * 4;  // M base in mtiles
    const int ptile = blockIdx.x;
    const int pbase = ptile * TILE_P;
    const bool producer = (tid == 0);
    const char* gW = (const char*)Wfrag2;

    if (tid == 0) {
        #pragma unroll
        for (int s = 0; s < STAGES; ++s) {
            mbar_init(full0 + s * 8, 1);    // expect_tx based
            mbar_init(empty0 + s * 8, 8);   // 8 consumer warps
        }
        mbar_init(fullA, 1);
    }
    __syncthreads();

    if (producer) {
        mbar_expect_tx(fullA, ATILE_BYTES);
        bulk_copy(sbase, &Ybuf[(size_t)ptile * AFRAG_HALFS], ATILE_BYTES, fullA);
        mbar_expect_tx(full0, BLK_BYTES);
        bulk_copy(ring, gW, BLK_BYTES, full0);   // block 0 -> stage 0
    }

    mbar_wait(fullA, 0);   // all threads: A resident

    const uint32_t abase = sbase;   // Afrag at smem offset 0

    #pragma unroll 1
    for (int ht = 0; ht < NTILES_H; ++ht) {
        const int stage = ht & 1;

        // producer: issue block ht+1 into the other stage
        if (producer) {
            const int bp = ht + 1;
            if (bp < NBLK) {
                const int sp = bp & 1;
                const int u = bp >> 1;          // usage index of stage sp
                if (u >= 1) mbar_wait(empty0 + sp * 8, (u - 1) & 1);
                mbar_expect_tx(full0 + sp * 8, BLK_BYTES);
                bulk_copy(ring + sp * BLK_BYTES, gW + (size_t)bp * BLK_BYTES,
                          BLK_BYTES, full0 + sp * 8);
            }
        }

        // consumer: single wait per ht (9 kc)
        mbar_wait(full0 + stage * 8, (ht >> 1) & 1);

        float acc[4][4][4];
        #pragma unroll
        for (int mt = 0; mt < 4; ++mt)
            #pragma unroll
            for (int nt = 0; nt < 4; ++nt)
                #pragma unroll
                for (int i = 0; i < 4; ++i) acc[mt][nt][i] = 0.0f;

        #pragma unroll
        for (int kc = 0; kc < NKC; ++kc) {
            const uint32_t bs = ring + stage * BLK_BYTES + kc * 4096
                              + wQ * 1024 + lane * 8;
            uint32_t bfr[4][2];
            #pragma unroll
            for (int nt = 0; nt < 4; ++nt)
                asm volatile("ld.shared.v2.u32 {%0,%1}, [%2];"
                             : "=r"(bfr[nt][0]), "=r"(bfr[nt][1])
                             : "r"(bs + nt * 256));

            uint32_t afr[4][4];
            #pragma unroll
            for (int mt = 0; mt < 4; ++mt) {
                uint32_t addr = abase + ((((wmt + mt) * NKC + kc) * 32 + lane) * 4) * 4;
                asm volatile("ld.shared.v4.u32 {%0,%1,%2,%3}, [%4];"
                             : "=r"(afr[mt][0]), "=r"(afr[mt][1]),
                               "=r"(afr[mt][2]), "=r"(afr[mt][3])
                             : "r"(addr));
            }

            #pragma unroll
            for (int mt = 0; mt < 4; ++mt)
                #pragma unroll
                for (int nt = 0; nt < 4; ++nt)
                    mma16(afr[mt], bfr[nt], acc[mt][nt]);
        }

        if (lane == 0) mbar_arrive(empty0 + stage * 8);

        // ---- epilogue: 8 consecutive h per lane -> 2x streaming STG.128/row ----
        const int g8 = lane >> 2;
        const int hb = ht * 128 + wQ * 32 + (lane & 3) * 8;
        float4 bb0 = *(const float4*)&bvec[hb];
        float4 bb1 = *(const float4*)&bvec[hb + 4];
        #pragma unroll
        for (int mt = 0; mt < 4; ++mt) {
            const int p0 = pbase + (wmt + mt) * 16 + g8;
            float* o0 = &out[(size_t)p0 * H_TOT + hb];
            float* o1 = &out[(size_t)(p0 + 8) * H_TOT + hb];
            float4 v0, v1;
            // row g8
            v0.x = acc[mt][0][0] + bb0.x;  v0.y = acc[mt][0][1] + bb0.y;
            v0.z = acc[mt][1][0] + bb0.z;  v0.w = acc[mt][1][1] + bb0.w;
            v1.x = acc[mt][2][0] + bb1.x;  v1.y = acc[mt][2][1] + bb1.y;
            v1.z = acc[mt][3][0] + bb1.z;  v1.w = acc[mt][3][1] + bb1.w;
            stcs4(o0 + 0, v0);
            stcs4(o0 + 4, v1);
            // row g8+8
            v0.x = acc[mt][0][2] + bb0.x;  v0.y = acc[mt][0][3] + bb0.y;
            v0.z = acc[mt][1][2] + bb0.z;  v0.w = acc[mt][1][3] + bb0.w;
            v1.x = acc[mt][2][2] + bb1.x;  v1.y = acc[mt][2][3] + bb1.y;
            v1.z = acc[mt][3][2] + bb1.z;  v1.w = acc[mt][3][3] + bb1.w;
            stcs4(o1 + 0, v0);
            stcs4(o1 + 4, v1);
        }
    }
}

extern "C" void kernel_launch(void* const* d_in, const int* in_sizes, int n_in,
                              void* d_out, int out_size) {
    const float* x = (const float*)d_in[0];   // (P, 2)
    const float* W = (const float*)d_in[1];   // (1024, 129)
    const float* b = (const float*)d_in[2];   // (1024,)
    float* out = (float*)d_out;               // (P, 1024)

    const int P = in_sizes[0] / 2;            // 131072
    const int ntiles = P / TILE_P;            // 1024

    wfrag_kernel<<<(H_TOT * NKPAD + 255) / 256, 256>>>(W);
    ygen_kernel<<<ntiles, 128>>>(x);

    cudaFuncSetAttribute(sph_mma_kernel,
                         cudaFuncAttributeMaxDynamicSharedMemorySize, SMEM_BYTES);
    sph_mma_kernel<<<ntiles, NTHREADS, SMEM_BYTES>>>(b, out);
}

// round 16
// speedup vs baseline: 1.4799x; 1.0230x over previous
#include <cuda_runtime.h>
#include <cuda_fp16.h>
#include <cstdint>
#include <math.h>

// SphericalFilter via mma.sync.m16n8k16 fp16 (fp32 accumulate).
// out[p,h] = sum_k Y[p,k] * W[h,k] + b[h];  P=131072, H=1024, K=129 (pad 144)
//
// R16 = R15 GEMM (1024 CTAs, 128p x 1024h, KCB=9 single-wait ring, Y
// precomputed) with prep consolidated into ONE kernel: blocks [0,576) do the
// W->B-fragment reorder, blocks [576,1600) generate Y tiles (constants
// computed inline, no cross-block dependency) -> the two phases overlap.

#define NK 129
#define NKPAD 144
#define NKC 9               // k-chunks of 16 per 128-h tile
#define H_TOT 1024
#define TILE_P 128
#define NTHREADS 256
#define NTILES_H 8
#define NBLK NTILES_H                 // 8 ring blocks (one per ht)
#define STAGES 2
#define BLK_BYTES (NKC * 4096)        // 36864

#define AFRAG_HALFS (8 * NKC * 32 * 8)          // 18432 halfs = 36864 B
#define ATILE_BYTES (AFRAG_HALFS * 2)           // 36864
#define RING_OFF ATILE_BYTES                    // 36864
#define RING_BYTES (STAGES * BLK_BYTES)         // 73728
#define MBAR_OFF (RING_OFF + RING_BYTES)        // 110592: full[2], empty[2], fullA
#define SMEM_BYTES (MBAR_OFF + 160)             // 110752 B

#define WFRAG_BLOCKS 576                        // 576*256 = 147456 = H*NKPAD

// Wfrag2: [htg 0..7][kc 0..8][wQ] 1KB units; inside: [nt][lane][reg] f16x2
__device__ __half Wfrag2[8 * NKC * 4 * 512];
// Y in A-fragment layout, one 36864B tile per 128 pixels
__device__ __half Ybuf[1024 * AFRAG_HALFS];     // 37.75 MB

// ---------------- helpers ----------------
__device__ __forceinline__ uint32_t smem_u32(const void* p) {
    uint32_t a;
    asm("{ .reg .u64 t; cvta.to.shared.u64 t, %1; cvt.u32.u64 %0, t; }" : "=r"(a) : "l"(p));
    return a;
}
__device__ __forceinline__ void mbar_init(uint32_t mbar, uint32_t cnt) {
    asm volatile("mbarrier.init.shared.b64 [%0], %1;" :: "r"(mbar), "r"(cnt) : "memory");
}
__device__ __forceinline__ void mbar_arrive(uint32_t mbar) {
    asm volatile("mbarrier.arrive.shared.b64 _, [%0];" :: "r"(mbar) : "memory");
}
__device__ __forceinline__ void mbar_expect_tx(uint32_t mbar, uint32_t bytes) {
    asm volatile("mbarrier.arrive.expect_tx.shared.b64 _, [%0], %1;"
                 :: "r"(mbar), "r"(bytes) : "memory");
}
__device__ __forceinline__ void mbar_wait(uint32_t mbar, uint32_t parity) {
    asm volatile(
        "{\n\t.reg .pred P;\n"
        "WL_%=:\n\t"
        "mbarrier.try_wait.parity.acquire.cta.shared::cta.b64 P, [%0], %1, 0x989680;\n\t"
        "@P bra.uni WD_%=;\n\t"
        "bra.uni WL_%=;\n"
        "WD_%=:\n\t}"
        :: "r"(mbar), "r"(parity) : "memory");
}
__device__ __forceinline__ void bulk_copy(uint32_t dst, const void* src,
                                          uint32_t bytes, uint32_t mbar) {
    asm volatile(
        "cp.async.bulk.shared::cta.global.mbarrier::complete_tx::bytes [%0], [%1], %2, [%3];"
        :: "r"(dst), "l"(src), "r"(bytes), "r"(mbar) : "memory");
}
__device__ __forceinline__ void bulk_s2g(void* dst, uint32_t src, uint32_t bytes) {
    asm volatile("cp.async.bulk.global.shared::cta.bulk_group [%0], [%1], %2;"
                 :: "l"(dst), "r"(src), "r"(bytes) : "memory");
}
__device__ __forceinline__ void bulk_commit() {
    asm volatile("cp.async.bulk.commit_group;" ::: "memory");
}
__device__ __forceinline__ void bulk_waitall() {
    asm volatile("cp.async.bulk.wait_group 0;" ::: "memory");
}
__device__ __forceinline__ void fence_async() {
    asm volatile("fence.proxy.async.shared::cta;" ::: "memory");
}

// A-fragment half index for element (row, k); one LDS.128 per (mt,kc,lane).
__device__ __forceinline__ int a_off(int row, int k) {
    int mt = row >> 4, half8 = (row >> 3) & 1, g = row & 7;
    int kc = k >> 4, khalf = (k >> 3) & 1, t = (k >> 1) & 3, kbit = k & 1;
    int lane = g * 4 + t;
    int reg = khalf * 2 + half8;
    return (((mt * NKC + kc) * 32 + lane) * 4 + reg) * 2 + kbit;
}

__device__ __forceinline__ void mma16(const uint32_t* a, const uint32_t* b, float* c) {
    asm volatile(
        "mma.sync.aligned.m16n8k16.row.col.f32.f16.f16.f32 "
        "{%0,%1,%2,%3}, {%4,%5,%6,%7}, {%8,%9}, {%0,%1,%2,%3};"
        : "+f"(c[0]), "+f"(c[1]), "+f"(c[2]), "+f"(c[3])
        : "r"(a[0]), "r"(a[1]), "r"(a[2]), "r"(a[3]), "r"(b[0]), "r"(b[1]));
}

__device__ __forceinline__ void stcs4(float* p, float4 v) {
    asm volatile("st.global.cs.v4.f32 [%0], {%1,%2,%3,%4};"
                 :: "l"(p), "f"(v.x), "f"(v.y), "f"(v.z), "f"(v.w) : "memory");
}

// ---------------- unified prep: wfrag blocks + ygen blocks ----------------
// blocks [0, 576):        W -> B-fragment layout
// blocks [576, 576+1024): Y tile generation -> Ybuf (A-fragment layout)
__global__ __launch_bounds__(NTHREADS, 2)
void prep_kernel(const float* __restrict__ W, const float* __restrict__ x) {
    extern __shared__ __half Af[];
    const int tid = threadIdx.x;
    const int bid = blockIdx.x;

    if (bid < WFRAG_BLOCKS) {
        // ---- W reorder: h = htg*128 + wQ*32 + hl; hl = t*8 + nt*2 + j ----
        int idx = bid * NTHREADS + tid;
        int h = idx / NKPAD;
        int k = idx - h * NKPAD;
        float v = (k < NK) ? W[h * NK + k] : 0.0f;
        int htg = h >> 7;
        int wQ = (h >> 5) & 3;
        int hl = h & 31;
        int t = hl >> 3;
        int rem = hl & 7;
        int nt = rem >> 1;
        int j = rem & 1;
        int n = t * 2 + j;
        int lane = n * 4 + ((k >> 1) & 3);
        int reg = (k >> 3) & 1;
        int kbit = k & 1;
        int kc = k >> 4;
        int block = (htg * NKC + kc) * 4 + wQ;
        Wfrag2[block * 512 + ((nt * 32 + lane) * 2 + reg) * 2 + kbit] = __float2half_rn(v);
        return;
    }

    // ---- Y generation (128 active threads per block, one pixel each) ----
    const int tile = bid - WFRAG_BLOCKS;
    if (tid < TILE_P) {
        float2 tp = ((const float2*)x)[tile * TILE_P + tid];
        const float theta = tp.x, phi = tp.y;
        const float ct = cosf(phi);
        const float st = sqrtf(fmaxf(1.0f - ct * ct, 0.0f));
        float pmm = 0.28209479177387814f;                 // sqrt(1/4pi)
        Af[a_off(tid, 64)] = __float2half_rn(1.7320508075688772f * ct * pmm);
        const float cth = cosf(theta), sth = sinf(theta);
        float cm = 1.0f, sm = 0.0f;
        #pragma unroll 4
        for (int m = 1; m <= 64; ++m) {
            // constants inline (parallel across 128 threads; cheap)
            float cx = -sqrtf((2.0f * m + 1.0f) / (2.0f * m));
            float cy = ((m & 1) ? -1.41421356237309515f : 1.41421356237309515f)
                       * sqrtf(2.0f * m + 3.0f);
            pmm *= cx * st;
            float c2 = cm * cth - sm * sth;
            float s2 = sm * cth + cm * sth;
            cm = c2; sm = s2;
            float v = cy * ct * pmm;
            Af[a_off(tid, 64 + m)] = __float2half_rn(v * cm);
            Af[a_off(tid, 64 - m)] = __float2half_rn(v * sm);
        }
        #pragma unroll
        for (int k = NK; k < NKPAD; ++k) Af[a_off(tid, k)] = __half(0.0f);
    }
    __syncthreads();
    fence_async();
    if (tid == 0) {
        bulk_s2g(&Ybuf[(size_t)tile * AFRAG_HALFS], smem_u32(Af), ATILE_BYTES);
        bulk_commit();
        bulk_waitall();
    }
}

// ---------------- main GEMM kernel ----------------
__global__ __launch_bounds__(NTHREADS, 2)
void sph_mma_kernel(const float* __restrict__ bvec,
                    float* __restrict__ out) {
    extern __shared__ __half smemh[];
    const uint32_t sbase = smem_u32(smemh);
    const uint32_t ring = sbase + RING_OFF;
    const uint32_t full0 = sbase + MBAR_OFF;
    const uint32_t empty0 = sbase + MBAR_OFF + 64;
    const uint32_t fullA = sbase + MBAR_OFF + 128;

    const int tid = threadIdx.x;
    const int lane = tid & 31;
    const int wid = tid >> 5;
    const int wQ = wid & 3;          // N quarter (32 h within a 128-h tile)
    const int wmt = (wid >> 2) * 4;  // M base in mtiles
    const int ptile = blockIdx.x;
    const int pbase = ptile * TILE_P;
    const bool producer = (tid == 0);
    const char* gW = (const char*)Wfrag2;

    if (tid == 0) {
        #pragma unroll
        for (int s = 0; s < STAGES; ++s) {
            mbar_init(full0 + s * 8, 1);    // expect_tx based
            mbar_init(empty0 + s * 8, 8);   // 8 consumer warps
        }
        mbar_init(fullA, 1);
    }
    __syncthreads();

    if (producer) {
        mbar_expect_tx(fullA, ATILE_BYTES);
        bulk_copy(sbase, &Ybuf[(size_t)ptile * AFRAG_HALFS], ATILE_BYTES, fullA);
        mbar_expect_tx(full0, BLK_BYTES);
        bulk_copy(ring, gW, BLK_BYTES, full0);   // block 0 -> stage 0
    }

    mbar_wait(fullA, 0);   // all threads: A resident

    const uint32_t abase = sbase;   // Afrag at smem offset 0

    #pragma unroll 1
    for (int ht = 0; ht < NTILES_H; ++ht) {
        const int stage = ht & 1;

        // producer: issue block ht+1 into the other stage
        if (producer) {
            const int bp = ht + 1;
            if (bp < NBLK) {
                const int sp = bp & 1;
                const int u = bp >> 1;          // usage index of stage sp
                if (u >= 1) mbar_wait(empty0 + sp * 8, (u - 1) & 1);
                mbar_expect_tx(full0 + sp * 8, BLK_BYTES);
                bulk_copy(ring + sp * BLK_BYTES, gW + (size_t)bp * BLK_BYTES,
                          BLK_BYTES, full0 + sp * 8);
            }
        }

        // consumer: single wait per ht (9 kc)
        mbar_wait(full0 + stage * 8, (ht >> 1) & 1);

        float acc[4][4][4];
        #pragma unroll
        for (int mt = 0; mt < 4; ++mt)
            #pragma unroll
            for (int nt = 0; nt < 4; ++nt)
                #pragma unroll
                for (int i = 0; i < 4; ++i) acc[mt][nt][i] = 0.0f;

        #pragma unroll
        for (int kc = 0; kc < NKC; ++kc) {
            const uint32_t bs = ring + stage * BLK_BYTES + kc * 4096
                              + wQ * 1024 + lane * 8;
            uint32_t bfr[4][2];
            #pragma unroll
            for (int nt = 0; nt < 4; ++nt)
                asm volatile("ld.shared.v2.u32 {%0,%1}, [%2];"
                             : "=r"(bfr[nt][0]), "=r"(bfr[nt][1])
                             : "r"(bs + nt * 256));

            uint32_t afr[4][4];
            #pragma unroll
            for (int mt = 0; mt < 4; ++mt) {
                uint32_t addr = abase + ((((wmt + mt) * NKC + kc) * 32 + lane) * 4) * 4;
                asm volatile("ld.shared.v4.u32 {%0,%1,%2,%3}, [%4];"
                             : "=r"(afr[mt][0]), "=r"(afr[mt][1]),
                               "=r"(afr[mt][2]), "=r"(afr[mt][3])
                             : "r"(addr));
            }

            #pragma unroll
            for (int mt = 0; mt < 4; ++mt)
                #pragma unroll
                for (int nt = 0; nt < 4; ++nt)
                    mma16(afr[mt], bfr[nt], acc[mt][nt]);
        }

        if (lane == 0) mbar_arrive(empty0 + stage * 8);

        // ---- epilogue: 8 consecutive h per lane -> 2x streaming STG.128/row ----
        const int g8 = lane >> 2;
        const int hb = ht * 128 + wQ * 32 + (lane & 3) * 8;
        float4 bb0 = *(const float4*)&bvec[hb];
        float4 bb1 = *(const float4*)&bvec[hb + 4];
        #pragma unroll
        for (int mt = 0; mt < 4; ++mt) {
            const int p0 = pbase + (wmt + mt) * 16 + g8;
            float* o0 = &out[(size_t)p0 * H_TOT + hb];
            float* o1 = &out[(size_t)(p0 + 8) * H_TOT + hb];
            float4 v0, v1;
            // row g8
            v0.x = acc[mt][0][0] + bb0.x;  v0.y = acc[mt][0][1] + bb0.y;
            v0.z = acc[mt][1][0] + bb0.z;  v0.w = acc[mt][1][1] + bb0.w;
            v1.x = acc[mt][2][0] + bb1.x;  v1.y = acc[mt][2][1] + bb1.y;
            v1.z = acc[mt][3][0] + bb1.z;  v1.w = acc[mt][3][1] + bb1.w;
            stcs4(o0 + 0, v0);
            stcs4(o0 + 4, v1);
            // row g8+8
            v0.x = acc[mt][0][2] + bb0.x;  v0.y = acc[mt][0][3] + bb0.y;
            v0.z = acc[mt][1][2] + bb0.z;  v0.w = acc[mt][1][3] + bb0.w;
            v1.x = acc[mt][2][2] + bb1.x;  v1.y = acc[mt][2][3] + bb1.y;
            v1.z = acc[mt][3][2] + bb1.z;  v1.w = acc[mt][3][3] + bb1.w;
            stcs4(o1 + 0, v0);
            stcs4(o1 + 4, v1);
        }
    }
}

extern "C" void kernel_launch(void* const* d_in, const int* in_sizes, int n_in,
                              void* d_out, int out_size) {
    const float* x = (const float*)d_in[0];   // (P, 2)
    const float* W = (const float*)d_in[1];   // (1024, 129)
    const float* b = (const float*)d_in[2];   // (1024,)
    float* out = (float*)d_out;               // (P, 1024)

    const int P = in_sizes[0] / 2;            // 131072
    const int ntiles = P / TILE_P;            // 1024

    cudaFuncSetAttribute(prep_kernel,
                         cudaFuncAttributeMaxDynamicSharedMemorySize, ATILE_BYTES);
    prep_kernel<<<WFRAG_BLOCKS + ntiles, NTHREADS, ATILE_BYTES>>>(W, x);

    cudaFuncSetAttribute(sph_mma_kernel,
                         cudaFuncAttributeMaxDynamicSharedMemorySize, SMEM_BYTES);
    sph_mma_kernel<<<ntiles, NTHREADS, SMEM_BYTES>>>(b, out);
}

// round 17
// speedup vs baseline: 1.5046x; 1.0167x over previous
#include <cuda_runtime.h>
#include <cuda_fp16.h>
#include <cstdint>
#include <math.h>

// SphericalFilter via mma.sync.m16n8k16 fp16 (fp32 accumulate).
// out[p,h] = sum_k Y[p,k] * W[h,k] + b[h];  P=131072, H=1024, K=129 (pad 144)
//
// R17 = R16 GEMM (1024 CTAs, 128p x 1024h, KCB=9 single-wait 2-stage ring,
// free-running warps, streaming STG epilogue) with Y generation folded back
// INTO the GEMM (computed into smem Afrag during W-ring warm-up) -- removes
// the ygen launch and the 75MB Ybuf DRAM roundtrip. Only wfrag prep remains.

#define NK 129
#define NKPAD 144
#define NKC 9               // k-chunks of 16 per 128-h tile
#define H_TOT 1024
#define TILE_P 128
#define NTHREADS 256
#define NTILES_H 8
#define NBLK NTILES_H                 // 8 ring blocks (one per ht)
#define STAGES 2
#define BLK_BYTES (NKC * 4096)        // 36864

#define AFRAG_HALFS (8 * NKC * 32 * 8)          // 18432 halfs = 36864 B
#define ATILE_BYTES (AFRAG_HALFS * 2)           // 36864
#define RING_OFF ATILE_BYTES                    // 36864
#define RING_BYTES (STAGES * BLK_BYTES)         // 73728
#define MBAR_OFF (RING_OFF + RING_BYTES)        // 110592: full[2], empty[2]
#define SMEM_BYTES (MBAR_OFF + 128)             // 110720 B

// Wfrag2: [htg 0..7][kc 0..8][wQ] 1KB units; inside: [nt][lane][reg] f16x2
__device__ __half Wfrag2[8 * NKC * 4 * 512];

// ---------------- helpers ----------------
__device__ __forceinline__ uint32_t smem_u32(const void* p) {
    uint32_t a;
    asm("{ .reg .u64 t; cvta.to.shared.u64 t, %1; cvt.u32.u64 %0, t; }" : "=r"(a) : "l"(p));
    return a;
}
__device__ __forceinline__ void mbar_init(uint32_t mbar, uint32_t cnt) {
    asm volatile("mbarrier.init.shared.b64 [%0], %1;" :: "r"(mbar), "r"(cnt) : "memory");
}
__device__ __forceinline__ void mbar_arrive(uint32_t mbar) {
    asm volatile("mbarrier.arrive.shared.b64 _, [%0];" :: "r"(mbar) : "memory");
}
__device__ __forceinline__ void mbar_expect_tx(uint32_t mbar, uint32_t bytes) {
    asm volatile("mbarrier.arrive.expect_tx.shared.b64 _, [%0], %1;"
                 :: "r"(mbar), "r"(bytes) : "memory");
}
__device__ __forceinline__ void mbar_wait(uint32_t mbar, uint32_t parity) {
    asm volatile(
        "{\n\t.reg .pred P;\n"
        "WL_%=:\n\t"
        "mbarrier.try_wait.parity.acquire.cta.shared::cta.b64 P, [%0], %1, 0x989680;\n\t"
        "@P bra.uni WD_%=;\n\t"
        "bra.uni WL_%=;\n"
        "WD_%=:\n\t}"
        :: "r"(mbar), "r"(parity) : "memory");
}
__device__ __forceinline__ void bulk_copy(uint32_t dst, const void* src,
                                          uint32_t bytes, uint32_t mbar) {
    asm volatile(
        "cp.async.bulk.shared::cta.global.mbarrier::complete_tx::bytes [%0], [%1], %2, [%3];"
        :: "r"(dst), "l"(src), "r"(bytes), "r"(mbar) : "memory");
}

// A-fragment half index for element (row, k); one LDS.128 per (mt,kc,lane).
__device__ __forceinline__ int a_off(int row, int k) {
    int mt = row >> 4, half8 = (row >> 3) & 1, g = row & 7;
    int kc = k >> 4, khalf = (k >> 3) & 1, t = (k >> 1) & 3, kbit = k & 1;
    int lane = g * 4 + t;
    int reg = khalf * 2 + half8;
    return (((mt * NKC + kc) * 32 + lane) * 4 + reg) * 2 + kbit;
}

__device__ __forceinline__ void mma16(const uint32_t* a, const uint32_t* b, float* c) {
    asm volatile(
        "mma.sync.aligned.m16n8k16.row.col.f32.f16.f16.f32 "
        "{%0,%1,%2,%3}, {%4,%5,%6,%7}, {%8,%9}, {%0,%1,%2,%3};"
        : "+f"(c[0]), "+f"(c[1]), "+f"(c[2]), "+f"(c[3])
        : "r"(a[0]), "r"(a[1]), "r"(a[2]), "r"(a[3]), "r"(b[0]), "r"(b[1]));
}

__device__ __forceinline__ void stcs4(float* p, float4 v) {
    asm volatile("st.global.cs.v4.f32 [%0], {%1,%2,%3,%4};"
                 :: "l"(p), "f"(v.x), "f"(v.y), "f"(v.z), "f"(v.w) : "memory");
}

// ---------------- W -> B-fragment reorder ----------------
// h = htg*128 + wQ*32 + hl;  hl = t*8 + nt*2 + j  (t = C-frag lane&3)
__global__ void wfrag_kernel(const float* __restrict__ W) {
    int idx = blockIdx.x * blockDim.x + threadIdx.x;
    if (idx >= H_TOT * NKPAD) return;
    int h = idx / NKPAD;
    int k = idx - h * NKPAD;
    float v = (k < NK) ? W[h * NK + k] : 0.0f;
    int htg = h >> 7;
    int wQ = (h >> 5) & 3;
    int hl = h & 31;
    int t = hl >> 3;
    int rem = hl & 7;
    int nt = rem >> 1;
    int j = rem & 1;
    int n = t * 2 + j;
    int lane = n * 4 + ((k >> 1) & 3);
    int reg = (k >> 3) & 1;
    int kbit = k & 1;
    int kc = k >> 4;
    int block = (htg * NKC + kc) * 4 + wQ;
    Wfrag2[block * 512 + ((nt * 32 + lane) * 2 + reg) * 2 + kbit] = __float2half_rn(v);
}

// ---------------- main fused kernel ----------------
__global__ __launch_bounds__(NTHREADS, 2)
void sph_mma_kernel(const float* __restrict__ x,
                    const float* __restrict__ bvec,
                    float* __restrict__ out) {
    extern __shared__ __half smemh[];
    __half* Afrag = smemh;
    const uint32_t sbase = smem_u32(smemh);
    const uint32_t ring = sbase + RING_OFF;
    const uint32_t full0 = sbase + MBAR_OFF;
    const uint32_t empty0 = sbase + MBAR_OFF + 64;

    const int tid = threadIdx.x;
    const int lane = tid & 31;
    const int wid = tid >> 5;
    const int wQ = wid & 3;          // N quarter (32 h within a 128-h tile)
    const int wmt = (wid >> 2) * 4;  // M base in mtiles
    const int ptile = blockIdx.x;
    const int pbase = ptile * TILE_P;
    const bool producer = (tid == 0);
    const char* gW = (const char*)Wfrag2;

    if (tid == 0) {
        #pragma unroll
        for (int s = 0; s < STAGES; ++s) {
            mbar_init(full0 + s * 8, 1);    // expect_tx based
            mbar_init(empty0 + s * 8, 8);   // 8 consumer warps
        }
    }
    __syncthreads();

    if (producer) {
        mbar_expect_tx(full0, BLK_BYTES);
        bulk_copy(ring, gW, BLK_BYTES, full0);   // block 0 -> stage 0
    }

    // ---- generate Y for 128 pixels into A-fragment smem (threads 0..127),
    //      overlapped with the W-ring warm-up ----
    if (tid < TILE_P) {
        float2 tp = ((const float2*)x)[pbase + tid];
        const float theta = tp.x, phi = tp.y;
        const float ct = cosf(phi);
        const float st = sqrtf(fmaxf(1.0f - ct * ct, 0.0f));
        float pmm = 0.28209479177387814f;                 // sqrt(1/4pi)
        Afrag[a_off(tid, 64)] = __float2half_rn(1.7320508075688772f * ct * pmm);
        const float cth = cosf(theta), sth = sinf(theta);
        float cm = 1.0f, sm = 0.0f;
        #pragma unroll 4
        for (int m = 1; m <= 64; ++m) {
            float cx = -sqrtf((2.0f * m + 1.0f) / (2.0f * m));
            float cy = ((m & 1) ? -1.41421356237309515f : 1.41421356237309515f)
                       * sqrtf(2.0f * m + 3.0f);
            pmm *= cx * st;
            float c2 = cm * cth - sm * sth;
            float s2 = sm * cth + cm * sth;
            cm = c2; sm = s2;
            float v = cy * ct * pmm;
            Afrag[a_off(tid, 64 + m)] = __float2half_rn(v * cm);
            Afrag[a_off(tid, 64 - m)] = __float2half_rn(v * sm);
        }
        #pragma unroll
        for (int k = NK; k < NKPAD; ++k) Afrag[a_off(tid, k)] = __half(0.0f);
    }
    __syncthreads();

    const uint32_t abase = sbase;   // Afrag at smem offset 0

    #pragma unroll 1
    for (int ht = 0; ht < NTILES_H; ++ht) {
        const int stage = ht & 1;

        // producer: issue block ht+1 into the other stage
        if (producer) {
            const int bp = ht + 1;
            if (bp < NBLK) {
                const int sp = bp & 1;
                const int u = bp >> 1;          // usage index of stage sp
                if (u >= 1) mbar_wait(empty0 + sp * 8, (u - 1) & 1);
                mbar_expect_tx(full0 + sp * 8, BLK_BYTES);
                bulk_copy(ring + sp * BLK_BYTES, gW + (size_t)bp * BLK_BYTES,
                          BLK_BYTES, full0 + sp * 8);
            }
        }

        // consumer: single wait per ht (9 kc)
        mbar_wait(full0 + stage * 8, (ht >> 1) & 1);

        float acc[4][4][4];
        #pragma unroll
        for (int mt = 0; mt < 4; ++mt)
            #pragma unroll
            for (int nt = 0; nt < 4; ++nt)
                #pragma unroll
                for (int i = 0; i < 4; ++i) acc[mt][nt][i] = 0.0f;

        #pragma unroll
        for (int kc = 0; kc < NKC; ++kc) {
            const uint32_t bs = ring + stage * BLK_BYTES + kc * 4096
                              + wQ * 1024 + lane * 8;
            uint32_t bfr[4][2];
            #pragma unroll
            for (int nt = 0; nt < 4; ++nt)
                asm volatile("ld.shared.v2.u32 {%0,%1}, [%2];"
                             : "=r"(bfr[nt][0]), "=r"(bfr[nt][1])
                             : "r"(bs + nt * 256));

            uint32_t afr[4][4];
            #pragma unroll
            for (int mt = 0; mt < 4; ++mt) {
                uint32_t addr = abase + ((((wmt + mt) * NKC + kc) * 32 + lane) * 4) * 4;
                asm volatile("ld.shared.v4.u32 {%0,%1,%2,%3}, [%4];"
                             : "=r"(afr[mt][0]), "=r"(afr[mt][1]),
                               "=r"(afr[mt][2]), "=r"(afr[mt][3])
                             : "r"(addr));
            }

            #pragma unroll
            for (int mt = 0; mt < 4; ++mt)
                #pragma unroll
                for (int nt = 0; nt < 4; ++nt)
                    mma16(afr[mt], bfr[nt], acc[mt][nt]);
        }

        if (lane == 0) mbar_arrive(empty0 + stage * 8);

        // ---- epilogue: 8 consecutive h per lane -> 2x streaming STG.128/row ----
        const int g8 = lane >> 2;
        const int hb = ht * 128 + wQ * 32 + (lane & 3) * 8;
        float4 bb0 = *(const float4*)&bvec[hb];
        float4 bb1 = *(const float4*)&bvec[hb + 4];
        #pragma unroll
        for (int mt = 0; mt < 4; ++mt) {
            const int p0 = pbase + (wmt + mt) * 16 + g8;
            float* o0 = &out[(size_t)p0 * H_TOT + hb];
            float* o1 = &out[(size_t)(p0 + 8) * H_TOT + hb];
            float4 v0, v1;
            // row g8
            v0.x = acc[mt][0][0] + bb0.x;  v0.y = acc[mt][0][1] + bb0.y;
            v0.z = acc[mt][1][0] + bb0.z;  v0.w = acc[mt][1][1] + bb0.w;
            v1.x = acc[mt][2][0] + bb1.x;  v1.y = acc[mt][2][1] + bb1.y;
            v1.z = acc[mt][3][0] + bb1.z;  v1.w = acc[mt][3][1] + bb1.w;
            stcs4(o0 + 0, v0);
            stcs4(o0 + 4, v1);
            // row g8+8
            v0.x = acc[mt][0][2] + bb0.x;  v0.y = acc[mt][0][3] + bb0.y;
            v0.z = acc[mt][1][2] + bb0.z;  v0.w = acc[mt][1][3] + bb0.w;
            v1.x = acc[mt][2][2] + bb1.x;  v1.y = acc[mt][2][3] + bb1.y;
            v1.z = acc[mt][3][2] + bb1.z;  v1.w = acc[mt][3][3] + bb1.w;
            stcs4(o1 + 0, v0);
            stcs4(o1 + 4, v1);
        }
    }
}

extern "C" void kernel_launch(void* const* d_in, const int* in_sizes, int n_in,
                              void* d_out, int out_size) {
    const float* x = (const float*)d_in[0];   // (P, 2)
    const float* W = (const float*)d_in[1];   // (1024, 129)
    const float* b = (const float*)d_in[2];   // (1024,)
    float* out = (float*)d_out;               // (P, 1024)

    const int P = in_sizes[0] / 2;            // 131072
    const int ntiles = P / TILE_P;            // 1024

    wfrag_kernel<<<(H_TOT * NKPAD + 255) / 256, 256>>>(W);

    cudaFuncSetAttribute(sph_mma_kernel,
                         cudaFuncAttributeMaxDynamicSharedMemorySize, SMEM_BYTES);
    sph_mma_kernel<<<ntiles, NTHREADS, SMEM_BYTES>>>(x, b, out);
}